// round 1
// baseline (speedup 1.0000x reference)
#include <cuda_runtime.h>
#include <math.h>

#define BSZ 64
#define NN  256
#define CC  512
#define NC  (NN*CC)     // 131072
#define NNN (NN*NN)     // 65536

// Scratch (no cudaMalloc allowed) — __device__ globals.
__device__ float g_b1[BSZ*NC];
__device__ float g_b2[BSZ*NC];
__device__ float g_b3[BSZ*NC];
__device__ float g_b4[BSZ*NC];
__device__ float g_S [BSZ*NNN];

// ---------------------------------------------------------------------------
// Generic batched SGEMM: C[b] (MxN) = op(A[b]) (MxK) @ op(B[b]) (KxN)
// TRANS_A: A element (m,k) read at A[k*lda + m]   (used for adj^T)
// TRANS_B: B element (k,n) read at B[n*ldb + k]   (used for W^T / P2^T)
// EPI: 0 = store acc
//      1 = store relu(acc)
//      2 = store relu(acc) + C_old        (accumulate into existing C)
//      3 = store relu(acc) + Add[b]       (add side buffer, same layout as C)
// Tiles: BM=BN=128, BK=8, 256 threads, 8x8 per thread.
// All dims here are multiples of the tile sizes (M=256, N in {256,512}, K in {256,512}).
// ---------------------------------------------------------------------------
template<int TRANS_A, int TRANS_B, int EPI>
__global__ __launch_bounds__(256)
void gemm_kernel(const float* __restrict__ A, long sA, int lda,
                 const float* __restrict__ B, long sB, int ldb,
                 float* __restrict__ C, long sC, int ldc,
                 const float* __restrict__ Add, long sAdd,
                 int M, int N, int K)
{
    const int BM = 128, BN = 128, BK = 8;
    __shared__ float As[BK][BM];
    __shared__ float Bs[BK][BN];

    const int b = blockIdx.z;
    const float* Ab = A + (long)b * sA;
    const float* Bb = B + (long)b * sB;
    float*       Cb = C + (long)b * sC;
    const float* Db = (EPI == 3) ? (Add + (long)b * sAdd) : nullptr;

    const int m0 = blockIdx.y * BM;
    const int n0 = blockIdx.x * BN;
    const int tid = threadIdx.x;
    const int trow = (tid >> 4) * 8;   // 16 groups of rows
    const int tcol = (tid & 15) * 8;   // 16 groups of cols

    float acc[8][8];
    #pragma unroll
    for (int i = 0; i < 8; i++)
        #pragma unroll
        for (int j = 0; j < 8; j++) acc[i][j] = 0.f;

    for (int k0 = 0; k0 < K; k0 += BK) {
        // ---- load A tile into As[k][m] ----
        if (TRANS_A) {
            int kk = tid >> 5;            // 0..7
            int mm = (tid & 31) * 4;      // 0..124
            float4 v = *(const float4*)&Ab[(long)(k0 + kk) * lda + m0 + mm];
            *(float4*)&As[kk][mm] = v;
        } else {
            int mm = tid >> 1;            // 0..127
            int c4 = (tid & 1) * 4;       // 0 or 4
            float4 v = *(const float4*)&Ab[(long)(m0 + mm) * lda + k0 + c4];
            As[c4 + 0][mm] = v.x; As[c4 + 1][mm] = v.y;
            As[c4 + 2][mm] = v.z; As[c4 + 3][mm] = v.w;
        }
        // ---- load B tile into Bs[k][n] ----
        if (TRANS_B) {
            int nn = tid >> 1;
            int c4 = (tid & 1) * 4;
            float4 v = *(const float4*)&Bb[(long)(n0 + nn) * ldb + k0 + c4];
            Bs[c4 + 0][nn] = v.x; Bs[c4 + 1][nn] = v.y;
            Bs[c4 + 2][nn] = v.z; Bs[c4 + 3][nn] = v.w;
        } else {
            int kk = tid >> 5;
            int nn = (tid & 31) * 4;
            float4 v = *(const float4*)&Bb[(long)(k0 + kk) * ldb + n0 + nn];
            *(float4*)&Bs[kk][nn] = v;
        }
        __syncthreads();

        #pragma unroll
        for (int k = 0; k < BK; k++) {
            float a[8], bb[8];
            *(float4*)&a[0]  = *(float4*)&As[k][trow];
            *(float4*)&a[4]  = *(float4*)&As[k][trow + 4];
            *(float4*)&bb[0] = *(float4*)&Bs[k][tcol];
            *(float4*)&bb[4] = *(float4*)&Bs[k][tcol + 4];
            #pragma unroll
            for (int i = 0; i < 8; i++)
                #pragma unroll
                for (int j = 0; j < 8; j++)
                    acc[i][j] = fmaf(a[i], bb[j], acc[i][j]);
        }
        __syncthreads();
    }

    // ---- epilogue ----
    #pragma unroll
    for (int i = 0; i < 8; i++) {
        long row = m0 + trow + i;
        float* crow = Cb + row * (long)ldc + n0 + tcol;
        #pragma unroll
        for (int jv = 0; jv < 2; jv++) {
            float4 v;
            v.x = acc[i][jv*4 + 0]; v.y = acc[i][jv*4 + 1];
            v.z = acc[i][jv*4 + 2]; v.w = acc[i][jv*4 + 3];
            if (EPI >= 1) {
                v.x = fmaxf(v.x, 0.f); v.y = fmaxf(v.y, 0.f);
                v.z = fmaxf(v.z, 0.f); v.w = fmaxf(v.w, 0.f);
            }
            if (EPI == 2) {
                float4 o = *(const float4*)&crow[jv*4];
                v.x += o.x; v.y += o.y; v.z += o.z; v.w += o.w;
            }
            if (EPI == 3) {
                const float4 o = *(const float4*)&Db[row * (long)ldc + n0 + tcol + jv*4];
                v.x += o.x; v.y += o.y; v.z += o.z; v.w += o.w;
            }
            *(float4*)&crow[jv*4] = v;
        }
    }
}

// ---------------------------------------------------------------------------
// Row softmax over last dim (256) of S, in place. One block (256 threads) / row.
// ---------------------------------------------------------------------------
__global__ __launch_bounds__(256)
void softmax_kernel(float* __restrict__ S)
{
    __shared__ float sm[8];
    const long row = blockIdx.x;
    float* p = S + row * (long)NN;
    const int t = threadIdx.x;

    float v = p[t];
    float m = v;
    #pragma unroll
    for (int o = 16; o > 0; o >>= 1) m = fmaxf(m, __shfl_xor_sync(0xffffffffu, m, o));
    if ((t & 31) == 0) sm[t >> 5] = m;
    __syncthreads();
    m = sm[0];
    #pragma unroll
    for (int i = 1; i < 8; i++) m = fmaxf(m, sm[i]);

    float e = expf(v - m);
    float s = e;
    #pragma unroll
    for (int o = 16; o > 0; o >>= 1) s += __shfl_xor_sync(0xffffffffu, s, o);
    __syncthreads();           // protect sm reuse
    if ((t & 31) == 0) sm[t >> 5] = s;
    __syncthreads();
    s = 0.f;
    #pragma unroll
    for (int i = 0; i < 8; i++) s += sm[i];

    p[t] = e / s;
}

// ---------------------------------------------------------------------------
extern "C" void kernel_launch(void* const* d_in, const int* in_sizes, int n_in,
                              void* d_out, int out_size)
{
    const float* f     = (const float*)d_in[0];   // (B,N,C)
    /* d_in[1] = rois: unused (all ROIs valid by construction) */
    const float* adj   = (const float*)d_in[2];   // (B,N,N)
    const float* Wse1  = (const float*)d_in[3];
    const float* Wse2  = (const float*)d_in[4];
    const float* Wst1  = (const float*)d_in[5];
    const float* Wst2  = (const float*)d_in[6];
    const float* Wst3  = (const float*)d_in[7];
    const float* Wst1b = (const float*)d_in[8];
    const float* Wst2b = (const float*)d_in[9];
    const float* Wst3b = (const float*)d_in[10];
    const float* Wsim1 = (const float*)d_in[11];
    const float* Wsim2 = (const float*)d_in[12];
    const float* Wsim3 = (const float*)d_in[13];
    float* out = (float*)d_out;

    float *b1, *b2, *b3, *b4, *S;
    cudaGetSymbolAddress((void**)&b1, g_b1);
    cudaGetSymbolAddress((void**)&b2, g_b2);
    cudaGetSymbolAddress((void**)&b3, g_b3);
    cudaGetSymbolAddress((void**)&b4, g_b4);
    cudaGetSymbolAddress((void**)&S,  g_S);

    const dim3 blk(256);
    const dim3 gNC(CC/128, NN/128, BSZ);   // (4,2,64)  M=256,N=512
    const dim3 gNN(NN/128, NN/128, BSZ);   // (2,2,64)  M=256,N=256

    // --- similarity graph: S = softmax((f Wse1^T)(f Wse2^T)^T, rows) ---
    gemm_kernel<0,1,0><<<gNC, blk>>>(f, NC, CC, Wse1, 0, CC, b1, NC, CC, nullptr, 0, NN, CC, CC);
    gemm_kernel<0,1,0><<<gNC, blk>>>(f, NC, CC, Wse2, 0, CC, b2, NC, CC, nullptr, 0, NN, CC, CC);
    gemm_kernel<0,1,0><<<gNN, blk>>>(b1, NC, CC, b2, NC, CC, S, NNN, NN, nullptr, 0, NN, NN, CC);
    softmax_kernel<<<BSZ*NN, blk>>>(S);

    // --- st branch: layer 1  (h -> b1) ---
    gemm_kernel<0,0,0><<<gNC, blk>>>(f, NC, CC, Wst1,  0, CC, b3, NC, CC, nullptr, 0, NN, CC, CC);
    gemm_kernel<0,0,0><<<gNC, blk>>>(f, NC, CC, Wst1b, 0, CC, b4, NC, CC, nullptr, 0, NN, CC, CC);
    gemm_kernel<0,0,1><<<gNC, blk>>>(adj, NNN, NN, b3, NC, CC, b1, NC, CC, nullptr, 0, NN, CC, NN);
    gemm_kernel<1,0,2><<<gNC, blk>>>(adj, NNN, NN, b4, NC, CC, b1, NC, CC, nullptr, 0, NN, CC, NN);
    // layer 2  (h2 -> b2)
    gemm_kernel<0,0,0><<<gNC, blk>>>(b1, NC, CC, Wst2,  0, CC, b3, NC, CC, nullptr, 0, NN, CC, CC);
    gemm_kernel<0,0,0><<<gNC, blk>>>(b1, NC, CC, Wst2b, 0, CC, b4, NC, CC, nullptr, 0, NN, CC, CC);
    gemm_kernel<0,0,1><<<gNC, blk>>>(adj, NNN, NN, b3, NC, CC, b2, NC, CC, nullptr, 0, NN, CC, NN);
    gemm_kernel<1,0,2><<<gNC, blk>>>(adj, NNN, NN, b4, NC, CC, b2, NC, CC, nullptr, 0, NN, CC, NN);
    // layer 3  (st -> b1)
    gemm_kernel<0,0,0><<<gNC, blk>>>(b2, NC, CC, Wst3,  0, CC, b3, NC, CC, nullptr, 0, NN, CC, CC);
    gemm_kernel<0,0,0><<<gNC, blk>>>(b2, NC, CC, Wst3b, 0, CC, b4, NC, CC, nullptr, 0, NN, CC, CC);
    gemm_kernel<0,0,1><<<gNC, blk>>>(adj, NNN, NN, b3, NC, CC, b1, NC, CC, nullptr, 0, NN, CC, NN);
    gemm_kernel<1,0,2><<<gNC, blk>>>(adj, NNN, NN, b4, NC, CC, b1, NC, CC, nullptr, 0, NN, CC, NN);

    // --- sim branch ---
    gemm_kernel<0,0,0><<<gNC, blk>>>(f, NC, CC, Wsim1, 0, CC, b3, NC, CC, nullptr, 0, NN, CC, CC);
    gemm_kernel<0,0,1><<<gNC, blk>>>(S, NNN, NN, b3, NC, CC, b2, NC, CC, nullptr, 0, NN, CC, NN);   // g  -> b2
    gemm_kernel<0,0,0><<<gNC, blk>>>(b2, NC, CC, Wsim2, 0, CC, b3, NC, CC, nullptr, 0, NN, CC, CC);
    gemm_kernel<0,0,1><<<gNC, blk>>>(S, NNN, NN, b3, NC, CC, b4, NC, CC, nullptr, 0, NN, CC, NN);   // g2 -> b4
    gemm_kernel<0,0,0><<<gNC, blk>>>(b4, NC, CC, Wsim3, 0, CC, b3, NC, CC, nullptr, 0, NN, CC, CC);
    // out = relu(S @ Y3) + st
    gemm_kernel<0,0,3><<<gNC, blk>>>(S, NNN, NN, b3, NC, CC, out, NC, CC, b1, NC, NN, CC, NN);
}

// round 3
// speedup vs baseline: 2.3587x; 2.3587x over previous
#include <cuda_runtime.h>
#include <cuda_bf16.h>
#include <math.h>
#include <stdint.h>

#define BSZ 64
#define NN  256
#define CC  512
#define NC  (NN*CC)     // 131072
#define NNN (NN*NN)     // 65536

// Scratch (no cudaMalloc allowed)
__device__ float g_b1[BSZ*NC];
__device__ float g_b2[BSZ*NC];
__device__ float g_b3[BSZ*NC];
__device__ float g_b4[BSZ*NC];
__device__ float g_S [BSZ*NNN];

// SMEM stage layout: Ah @0 (8KB) | Al @8K | Bh @16K | Bl @24K ; two stages.
#define STG        32768
#define SMEM_TOTAL (2*STG)

__device__ __forceinline__ uint32_t smem_u32(const void* p) {
    uint32_t a;
    asm("{ .reg .u64 t; cvta.to.shared.u64 t, %1; cvt.u32.u64 %0, t; }" : "=r"(a) : "l"(p));
    return a;
}

// [row][k] layout, 128 rows x 64B; swizzle keeps ldmatrix phases conflict-free
__device__ __forceinline__ uint32_t off_rk(uint32_t r, uint32_t cb) {
    return r * 64u + ((((cb >> 4) ^ ((r >> 1) & 3u)) & 3u) << 4) + (cb & 15u);
}
// [k][col] layout, 32 rows x 256B
__device__ __forceinline__ uint32_t off_kn(uint32_t k, uint32_t cb) {
    uint32_t ch = (cb >> 4) ^ (k & 7u);
    return k * 256u + (ch << 4) + (cb & 15u);
}

__device__ __forceinline__ void ldsm4(uint32_t& r0, uint32_t& r1, uint32_t& r2, uint32_t& r3, uint32_t a) {
    asm volatile("ldmatrix.sync.aligned.m8n8.x4.shared.b16 {%0,%1,%2,%3}, [%4];"
                 : "=r"(r0), "=r"(r1), "=r"(r2), "=r"(r3) : "r"(a));
}
__device__ __forceinline__ void ldsm4t(uint32_t& r0, uint32_t& r1, uint32_t& r2, uint32_t& r3, uint32_t a) {
    asm volatile("ldmatrix.sync.aligned.m8n8.x4.trans.shared.b16 {%0,%1,%2,%3}, [%4];"
                 : "=r"(r0), "=r"(r1), "=r"(r2), "=r"(r3) : "r"(a));
}
__device__ __forceinline__ void mma16816(float* c, const uint32_t* a, const uint32_t* b) {
    asm volatile(
        "mma.sync.aligned.m16n8k16.row.col.f32.bf16.bf16.f32 "
        "{%0,%1,%2,%3}, {%4,%5,%6,%7}, {%8,%9}, {%0,%1,%2,%3};"
        : "+f"(c[0]), "+f"(c[1]), "+f"(c[2]), "+f"(c[3])
        : "r"(a[0]), "r"(a[1]), "r"(a[2]), "r"(a[3]), "r"(b[0]), "r"(b[1]));
}

// Convert 8 fp32 -> 8 bf16 hi + 8 bf16 lo, write 16B each.
__device__ __forceinline__ void cvt_store8(const float4 v0, const float4 v1,
                                           char* ph, char* pl) {
    float v[8] = {v0.x, v0.y, v0.z, v0.w, v1.x, v1.y, v1.z, v1.w};
    unsigned short hs[8], ls[8];
    #pragma unroll
    for (int e = 0; e < 8; e++) {
        __nv_bfloat16 hb = __float2bfloat16_rn(v[e]);
        float lf = v[e] - __bfloat162float(hb);
        __nv_bfloat16 lb = __float2bfloat16_rn(lf);
        hs[e] = *(unsigned short*)&hb;
        ls[e] = *(unsigned short*)&lb;
    }
    *(uint4*)ph = *(uint4*)hs;
    *(uint4*)pl = *(uint4*)ls;
}

// Stage one 128x32 operand tile (fp32 -> bf16 hi/lo split).
// T=0: source row-major rows=tile rows (m or n), ld over k.  layout [r][k].
// T=1: source row-major rows=k (transposed operand).          layout [k][c].
template<int T>
__device__ __forceinline__ void stage_tile(const float* __restrict__ src, int ld,
                                           int k0, int r0,
                                           char* sh, char* sl, int tid) {
    if (T == 0) {
        #pragma unroll
        for (int it = 0; it < 2; it++) {
            int idx = it * 256 + tid;
            int r = idx >> 2, cb8 = (idx & 3) * 8;
            const float* p = src + (long)(r0 + r) * ld + k0 + cb8;
            float4 a = *(const float4*)p;
            float4 b = *(const float4*)(p + 4);
            uint32_t off = off_rk((uint32_t)r, (uint32_t)cb8 * 2);
            cvt_store8(a, b, sh + off, sl + off);
        }
    } else {
        #pragma unroll
        for (int it = 0; it < 2; it++) {
            int idx = it * 256 + tid;
            int kr = idx >> 4, cb8 = (idx & 15) * 8;
            const float* p = src + (long)(k0 + kr) * ld + r0 + cb8;
            float4 a = *(const float4*)p;
            float4 b = *(const float4*)(p + 4);
            uint32_t off = off_kn((uint32_t)kr, (uint32_t)cb8 * 2);
            cvt_store8(a, b, sh + off, sl + off);
        }
    }
}

// ---------------------------------------------------------------------------
// bf16x2-split (3-product) tensor-core GEMM.  C[b](M x N) = op(A[b]) @ op(B[b])
//   TA=0: A row-major (M,K).  TA=1: A[m][k] = src[k*lda+m] (adj^T).
//   TB=0: B source (N,K) row-major.  TB=1: B[n][k] = src[k*ldb+n].
//   EPI: 0 store | 1 relu | 2 relu + C_old | 3 relu + Add
// CTA 128x128, BK=32, 256 thr; warp tile 32x64 (warp_m=wid&3, warp_n=wid>>2).
// ---------------------------------------------------------------------------
template<int TA, int TB, int EPI>
__global__ __launch_bounds__(256)
void tc_gemm(const float* __restrict__ A, long sA, int lda,
             const float* __restrict__ B, long sB, int ldb,
             float* __restrict__ C, long sC, int ldc,
             const float* __restrict__ Add, long sAdd, int K)
{
    extern __shared__ char smem[];
    const int tid = threadIdx.x, lane = tid & 31, wid = tid >> 5;
    const int b  = blockIdx.z;
    const int m0 = blockIdx.y * 128;
    const int n0 = blockIdx.x * 128;
    const float* Ab = A + (long)b * sA;
    const float* Bb = B + (long)b * sB;
    float*       Cb = C + (long)b * sC;

    const int am = (wid & 3) * 32;   // warp rows
    const int bn = (wid >> 2) * 64;  // warp cols

    float acc[2][8][4];
    #pragma unroll
    for (int i = 0; i < 2; i++)
        #pragma unroll
        for (int j = 0; j < 8; j++)
            #pragma unroll
            for (int e = 0; e < 4; e++) acc[i][j][e] = 0.f;

    const int nch = K >> 5;

    stage_tile<TA>(Ab, lda, 0, m0, smem,          smem + 8192,  tid);
    stage_tile<TB>(Bb, ldb, 0, n0, smem + 16384,  smem + 24576, tid);
    __syncthreads();

    for (int ch = 0; ch < nch; ch++) {
        const int d = ch & 1;
        char* cur = smem + d * STG;
        if (ch + 1 < nch) {
            char* nxt = smem + (d ^ 1) * STG;
            stage_tile<TA>(Ab, lda, (ch + 1) << 5, m0, nxt,         nxt + 8192,  tid);
            stage_tile<TB>(Bb, ldb, (ch + 1) << 5, n0, nxt + 16384, nxt + 24576, tid);
        }
        const uint32_t uAh = smem_u32(cur);
        const uint32_t uAl = uAh + 8192;
        const uint32_t uBh = uAh + 16384;
        const uint32_t uBl = uAh + 24576;

        #pragma unroll
        for (int ks = 0; ks < 2; ks++) {
            // ---- A fragments (2 m-tiles, hi+lo) ----
            uint32_t Ah[2][4], Al[2][4];
            #pragma unroll
            for (int mt = 0; mt < 2; mt++) {
                uint32_t off;
                if (!TA) {
                    uint32_t row = (uint32_t)(am + mt * 16 + (lane & 15));
                    uint32_t cb  = (uint32_t)(ks * 32 + ((lane >> 4) << 4));
                    off = off_rk(row, cb);
                } else {
                    uint32_t grp = lane >> 3, t8 = lane & 7;
                    uint32_t k   = (uint32_t)(ks * 16) + ((grp >> 1) << 3) + t8;
                    uint32_t cb  = (uint32_t)(am + mt * 16 + ((grp & 1) << 3)) * 2;
                    off = off_kn(k, cb);
                }
                if (!TA) {
                    ldsm4(Ah[mt][0], Ah[mt][1], Ah[mt][2], Ah[mt][3], uAh + off);
                    ldsm4(Al[mt][0], Al[mt][1], Al[mt][2], Al[mt][3], uAl + off);
                } else {
                    ldsm4t(Ah[mt][0], Ah[mt][1], Ah[mt][2], Ah[mt][3], uAh + off);
                    ldsm4t(Al[mt][0], Al[mt][1], Al[mt][2], Al[mt][3], uAl + off);
                }
            }
            // ---- B fragments (8 n-tiles as 4 x4 loads, hi+lo) ----
            uint32_t Bh[8][2], Bl[8][2];
            #pragma unroll
            for (int p = 0; p < 4; p++) {
                uint32_t off;
                if (!TB) {
                    uint32_t row = (uint32_t)(bn + p * 16 + (lane & 15));
                    uint32_t cb  = (uint32_t)(ks * 32 + ((lane >> 4) << 4));
                    off = off_rk(row, cb);
                } else {
                    uint32_t grp = lane >> 3, t8 = lane & 7;
                    uint32_t k   = (uint32_t)(ks * 16) + ((grp >> 1) << 3) + t8;
                    uint32_t cb  = (uint32_t)(bn + p * 16 + ((grp & 1) << 3)) * 2;
                    off = off_kn(k, cb);
                }
                uint32_t r0, r1, r2, r3;
                if (!TB) ldsm4 (r0, r1, r2, r3, uBh + off);
                else     ldsm4t(r0, r1, r2, r3, uBh + off);
                Bh[2*p][0] = r0; Bh[2*p][1] = r2; Bh[2*p+1][0] = r1; Bh[2*p+1][1] = r3;
                if (!TB) ldsm4 (r0, r1, r2, r3, uBl + off);
                else     ldsm4t(r0, r1, r2, r3, uBl + off);
                Bl[2*p][0] = r0; Bl[2*p][1] = r2; Bl[2*p+1][0] = r1; Bl[2*p+1][1] = r3;
            }
            // ---- 3-product MMAs ----
            #pragma unroll
            for (int mt = 0; mt < 2; mt++)
                #pragma unroll
                for (int nt = 0; nt < 8; nt++) {
                    mma16816(acc[mt][nt], Ah[mt], Bh[nt]);
                    mma16816(acc[mt][nt], Ah[mt], Bl[nt]);
                    mma16816(acc[mt][nt], Al[mt], Bh[nt]);
                }
        }
        __syncthreads();
    }

    // ---- epilogue ----
    #pragma unroll
    for (int mt = 0; mt < 2; mt++) {
        #pragma unroll
        for (int half = 0; half < 2; half++) {
            int row = m0 + am + mt * 16 + (lane >> 2) + half * 8;
            float* crow = Cb + (long)row * ldc + n0 + bn + (lane & 3) * 2;
            const float* arow = (EPI == 3)
                ? Add + (long)b * sAdd + (long)row * ldc + n0 + bn + (lane & 3) * 2 : nullptr;
            #pragma unroll
            for (int nt = 0; nt < 8; nt++) {
                float x = acc[mt][nt][half * 2 + 0];
                float y = acc[mt][nt][half * 2 + 1];
                if (EPI >= 1) { x = fmaxf(x, 0.f); y = fmaxf(y, 0.f); }
                if (EPI == 2) { float2 o = *(const float2*)&crow[nt * 8]; x += o.x; y += o.y; }
                if (EPI == 3) { float2 o = *(const float2*)&arow[nt * 8]; x += o.x; y += o.y; }
                float2 v; v.x = x; v.y = y;
                *(float2*)&crow[nt * 8] = v;
            }
        }
    }
}

// ---------------------------------------------------------------------------
// Row softmax over last dim (256), in place.
// ---------------------------------------------------------------------------
__global__ __launch_bounds__(256)
void softmax_kernel(float* __restrict__ S)
{
    __shared__ float sm[8];
    const long row = blockIdx.x;
    float* p = S + row * (long)NN;
    const int t = threadIdx.x;

    float v = p[t];
    float m = v;
    #pragma unroll
    for (int o = 16; o > 0; o >>= 1) m = fmaxf(m, __shfl_xor_sync(0xffffffffu, m, o));
    if ((t & 31) == 0) sm[t >> 5] = m;
    __syncthreads();
    m = sm[0];
    #pragma unroll
    for (int i = 1; i < 8; i++) m = fmaxf(m, sm[i]);

    float e = expf(v - m);
    float s = e;
    #pragma unroll
    for (int o = 16; o > 0; o >>= 1) s += __shfl_xor_sync(0xffffffffu, s, o);
    __syncthreads();
    if ((t & 31) == 0) sm[t >> 5] = s;
    __syncthreads();
    s = 0.f;
    #pragma unroll
    for (int i = 0; i < 8; i++) s += sm[i];

    p[t] = e / s;
}

// ---------------------------------------------------------------------------
extern "C" void kernel_launch(void* const* d_in, const int* in_sizes, int n_in,
                              void* d_out, int out_size)
{
    const float* f     = (const float*)d_in[0];
    const float* adj   = (const float*)d_in[2];
    const float* Wse1  = (const float*)d_in[3];
    const float* Wse2  = (const float*)d_in[4];
    const float* Wst1  = (const float*)d_in[5];
    const float* Wst2  = (const float*)d_in[6];
    const float* Wst3  = (const float*)d_in[7];
    const float* Wst1b = (const float*)d_in[8];
    const float* Wst2b = (const float*)d_in[9];
    const float* Wst3b = (const float*)d_in[10];
    const float* Wsim1 = (const float*)d_in[11];
    const float* Wsim2 = (const float*)d_in[12];
    const float* Wsim3 = (const float*)d_in[13];
    float* out = (float*)d_out;

    float *b1, *b2, *b3, *b4, *S;
    cudaGetSymbolAddress((void**)&b1, g_b1);
    cudaGetSymbolAddress((void**)&b2, g_b2);
    cudaGetSymbolAddress((void**)&b3, g_b3);
    cudaGetSymbolAddress((void**)&b4, g_b4);
    cudaGetSymbolAddress((void**)&S,  g_S);

    cudaFuncSetAttribute(tc_gemm<0,0,0>, cudaFuncAttributeMaxDynamicSharedMemorySize, SMEM_TOTAL);
    cudaFuncSetAttribute(tc_gemm<0,1,0>, cudaFuncAttributeMaxDynamicSharedMemorySize, SMEM_TOTAL);
    cudaFuncSetAttribute(tc_gemm<0,1,1>, cudaFuncAttributeMaxDynamicSharedMemorySize, SMEM_TOTAL);
    cudaFuncSetAttribute(tc_gemm<1,1,2>, cudaFuncAttributeMaxDynamicSharedMemorySize, SMEM_TOTAL);
    cudaFuncSetAttribute(tc_gemm<0,1,3>, cudaFuncAttributeMaxDynamicSharedMemorySize, SMEM_TOTAL);

    const dim3 blk(256);
    const dim3 g1(CC/128, NN/128, BSZ);   // (4,2,64): M=256, N=512
    const dim3 g3(NN/128, NN/128, BSZ);   // (2,2,64): M=256, N=256
    const int SM = SMEM_TOTAL;

    // similarity graph: S = softmax((f Wse1^T)(f Wse2^T)^T)
    tc_gemm<0,0,0><<<g1, blk, SM>>>(f, NC, CC, Wse1, 0, CC, b1, NC, CC, nullptr, 0, CC);
    tc_gemm<0,0,0><<<g1, blk, SM>>>(f, NC, CC, Wse2, 0, CC, b2, NC, CC, nullptr, 0, CC);
    tc_gemm<0,0,0><<<g3, blk, SM>>>(b1, NC, CC, b2, NC, CC, S, NNN, NN, nullptr, 0, CC);
    softmax_kernel<<<BSZ*NN, blk>>>(S);

    // st branch layer 1 -> b1
    tc_gemm<0,1,0><<<g1, blk, SM>>>(f, NC, CC, Wst1,  0, CC, b3, NC, CC, nullptr, 0, CC);
    tc_gemm<0,1,0><<<g1, blk, SM>>>(f, NC, CC, Wst1b, 0, CC, b4, NC, CC, nullptr, 0, CC);
    tc_gemm<0,1,1><<<g1, blk, SM>>>(adj, NNN, NN, b3, NC, CC, b1, NC, CC, nullptr, 0, NN);
    tc_gemm<1,1,2><<<g1, blk, SM>>>(adj, NNN, NN, b4, NC, CC, b1, NC, CC, nullptr, 0, NN);
    // layer 2 -> b2
    tc_gemm<0,1,0><<<g1, blk, SM>>>(b1, NC, CC, Wst2,  0, CC, b3, NC, CC, nullptr, 0, CC);
    tc_gemm<0,1,0><<<g1, blk, SM>>>(b1, NC, CC, Wst2b, 0, CC, b4, NC, CC, nullptr, 0, CC);
    tc_gemm<0,1,1><<<g1, blk, SM>>>(adj, NNN, NN, b3, NC, CC, b2, NC, CC, nullptr, 0, NN);
    tc_gemm<1,1,2><<<g1, blk, SM>>>(adj, NNN, NN, b4, NC, CC, b2, NC, CC, nullptr, 0, NN);
    // layer 3 -> b1
    tc_gemm<0,1,0><<<g1, blk, SM>>>(b2, NC, CC, Wst3,  0, CC, b3, NC, CC, nullptr, 0, CC);
    tc_gemm<0,1,0><<<g1, blk, SM>>>(b2, NC, CC, Wst3b, 0, CC, b4, NC, CC, nullptr, 0, CC);
    tc_gemm<0,1,1><<<g1, blk, SM>>>(adj, NNN, NN, b3, NC, CC, b1, NC, CC, nullptr, 0, NN);
    tc_gemm<1,1,2><<<g1, blk, SM>>>(adj, NNN, NN, b4, NC, CC, b1, NC, CC, nullptr, 0, NN);

    // sim branch
    tc_gemm<0,1,0><<<g1, blk, SM>>>(f, NC, CC, Wsim1, 0, CC, b3, NC, CC, nullptr, 0, CC);
    tc_gemm<0,1,1><<<g1, blk, SM>>>(S, NNN, NN, b3, NC, CC, b2, NC, CC, nullptr, 0, NN);
    tc_gemm<0,1,0><<<g1, blk, SM>>>(b2, NC, CC, Wsim2, 0, CC, b3, NC, CC, nullptr, 0, CC);
    tc_gemm<0,1,1><<<g1, blk, SM>>>(S, NNN, NN, b3, NC, CC, b4, NC, CC, nullptr, 0, NN);
    tc_gemm<0,1,0><<<g1, blk, SM>>>(b4, NC, CC, Wsim3, 0, CC, b3, NC, CC, nullptr, 0, CC);
    // out = relu(S @ Y3) + st
    tc_gemm<0,1,3><<<g1, blk, SM>>>(S, NNN, NN, b3, NC, CC, out, NC, CC, b1, NC, NN);
}